// round 11
// baseline (speedup 1.0000x reference)
#include <cuda_runtime.h>
#include <cuda_bf16.h>
#include <cstdint>

#define NNODE 100000
#define NPAD  100096
#define NEDGE 200000
#define NGRAPH 5000
#define NLAYER 5
#define KA 304      // h2 fp32 stride (300 padded to 304)
#define NCH1 10     // K chunks for GEMM1 (K=320)
#define NCH2 19     // K chunks for GEMM2 (K=608)
#define NB1 640
#define NB2 320

// ---------------- device scratch ----------------
// chunk-major, pre-swizzled operand arrays: [kchunk][row][32 bf16]
__device__ float g_h2[(size_t)NNODE * KA];                  // pre-norm layer output (fp32)
__device__ __nv_bfloat16 g_aggh[(size_t)NCH1 * NPAD * 32];  // agg split hi
__device__ __nv_bfloat16 g_aggl[(size_t)NCH1 * NPAD * 32];  // agg split lo
__device__ __nv_bfloat16 g_Th[(size_t)NCH2 * NPAD * 32];    // hidden split hi
__device__ __nv_bfloat16 g_Tl[(size_t)NCH2 * NPAD * 32];    // hidden split lo
__device__ __nv_bfloat16 g_B1h[NLAYER * NCH1 * 640 * 32];   // W1^T split [l][kc][n][32]
__device__ __nv_bfloat16 g_B1l[NLAYER * NCH1 * 640 * 32];
__device__ __nv_bfloat16 g_B2h[NLAYER * NCH2 * 320 * 32];   // W2^T split [l][kc][n][32]
__device__ __nv_bfloat16 g_B2l[NLAYER * NCH2 * 320 * 32];
__device__ float g_b1p[NLAYER * NB1];
__device__ float g_b2p[NLAYER * NB2];
__device__ float g_e1p[NLAYER * 6 * KA];
__device__ float g_e2p[NLAYER * 3 * KA];
__device__ float g_scale[KA];
__device__ float g_shift[KA];
__device__ float g_stats[2 * KA];
__device__ int   g_deg[NNODE];
__device__ int   g_cursor[NNODE];
__device__ int   g_rowptr[NNODE + 1];
__device__ int   g_srclist[NEDGE];
__device__ int   g_ecnt[(size_t)NNODE * 9];
__device__ int   g_gstart[NGRAPH + 1];
__device__ float g_ginv[NGRAPH];

// ---------------- helpers ----------------
__device__ __forceinline__ uint32_t smem_u32(const void* p) {
    uint32_t a;
    asm("{ .reg .u64 t; cvta.to.shared.u64 t, %1; cvt.u32.u64 %0, t; }" : "=r"(a) : "l"(p));
    return a;
}
__device__ __forceinline__ void bulk_g2s(uint32_t dst, const void* src, uint32_t bytes, uint32_t mbar) {
    asm volatile("cp.async.bulk.shared::cta.global.mbarrier::complete_tx::bytes [%0], [%1], %2, [%3];"
                 :: "r"(dst), "l"(src), "r"(bytes), "r"(mbar) : "memory");
}
#define MBARRIER_INIT(addr, cnt) \
    asm volatile("mbarrier.init.shared.b64 [%0], %1;" :: "r"(addr), "r"(cnt) : "memory")
#define MBARRIER_ARRIVE(addr) \
    asm volatile("mbarrier.arrive.shared.b64 _, [%0];" :: "r"(addr) : "memory")
#define MBARRIER_EXPECT_TX(addr, bytes) \
    asm volatile("mbarrier.arrive.expect_tx.shared.b64 _, [%0], %1;" :: "r"(addr), "r"(bytes) : "memory")
#define MBARRIER_WAIT_PARITY(mbar_smem_addr, phase_parity) do { \
    uint32_t _mbar = (uint32_t)(mbar_smem_addr); \
    uint32_t _parity = (uint32_t)(phase_parity); \
    uint32_t _done; \
    asm volatile("{\n\t.reg .pred p;\n\t" \
        "mbarrier.try_wait.parity.acquire.cta.shared::cta.b64 p, [%1], %2;\n\t" \
        "selp.b32 %0, 1, 0, p;\n\t}" \
        : "=r"(_done) : "r"(_mbar), "r"(_parity) : "memory"); \
    if (!_done) { \
        asm volatile("{\n\t.reg .pred P1;\n\t" \
            "WAIT_LOOP_%=:\n\t" \
            "mbarrier.try_wait.parity.acquire.cta.shared::cta.b64 P1, [%0], %1, 0x989680;\n\t" \
            "@P1 bra.uni WAIT_DONE_%=;\n\t" \
            "bra.uni WAIT_LOOP_%=;\n\t" \
            "WAIT_DONE_%=:\n\t}" \
            :: "r"(_mbar), "r"(_parity) : "memory"); \
    } \
} while (0)

__device__ __forceinline__ void ldsm_x4(uint32_t* r, uint32_t addr) {
    asm volatile("ldmatrix.sync.aligned.m8n8.x4.shared.b16 {%0,%1,%2,%3}, [%4];"
                 : "=r"(r[0]), "=r"(r[1]), "=r"(r[2]), "=r"(r[3]) : "r"(addr));
}
__device__ __forceinline__ void ldsm_x2(uint32_t* r, uint32_t addr) {
    asm volatile("ldmatrix.sync.aligned.m8n8.x2.shared.b16 {%0,%1}, [%2];"
                 : "=r"(r[0]), "=r"(r[1]) : "r"(addr));
}
__device__ __forceinline__ void mma_bf16(float* d, const uint32_t* a, const uint32_t* b) {
    asm volatile("mma.sync.aligned.m16n8k16.row.col.f32.bf16.bf16.f32 "
                 "{%0,%1,%2,%3}, {%4,%5,%6,%7}, {%8,%9}, {%0,%1,%2,%3};"
                 : "+f"(d[0]), "+f"(d[1]), "+f"(d[2]), "+f"(d[3])
                 : "r"(a[0]), "r"(a[1]), "r"(a[2]), "r"(a[3]), "r"(b[0]), "r"(b[1]));
}

// swizzled byte offset within a tile: row r (64B rows), 16B chunk cc (0..3)
__device__ __forceinline__ uint32_t swz64(int r, int cc) {
    return (uint32_t)(r * 64 + ((cc ^ ((r >> 1) & 3)) << 4));
}

// ---------------- setup kernels ----------------
__global__ void k_zero() {
    int idx = blockIdx.x * blockDim.x + threadIdx.x;
    if (idx < NNODE) { g_deg[idx] = 0; g_cursor[idx] = 0; }
    if (idx < NNODE * 9) g_ecnt[idx] = 0;
}

__global__ void k_prep_b1(const float* __restrict__ W1, const float* __restrict__ b1) {
    int idx = blockIdx.x * blockDim.x + threadIdx.x;
    if (idx < NLAYER * 640 * 320) {
        int k = idx % 320;
        int n = (idx / 320) % 640;
        int l = idx / (320 * 640);
        float w = (k < 300 && n < 600) ? W1[((size_t)l * 300 + k) * 600 + n] : 0.f;
        __nv_bfloat16 h = __float2bfloat16(w);
        int kc = k >> 5, kin = k & 31;
        int cc = kin >> 3;
        int pos = ((cc ^ ((n >> 1) & 3)) << 3) | (kin & 7);
        size_t dst = (((size_t)l * NCH1 + kc) * 640 + n) * 32 + pos;
        g_B1h[dst] = h;
        g_B1l[dst] = __float2bfloat16(w - __bfloat162float(h));
    }
    if (idx < NLAYER * NB1) {
        int n = idx % NB1, l = idx / NB1;
        g_b1p[idx] = (n < 600) ? b1[l * 600 + n] : 0.f;
    }
}

__global__ void k_prep_b2(const float* __restrict__ W2, const float* __restrict__ b2) {
    int idx = blockIdx.x * blockDim.x + threadIdx.x;
    if (idx < NLAYER * 320 * 608) {
        int k = idx % 608;
        int n = (idx / 608) % 320;
        int l = idx / (608 * 320);
        float w = (k < 600 && n < 300) ? W2[((size_t)l * 600 + k) * 300 + n] : 0.f;
        __nv_bfloat16 h = __float2bfloat16(w);
        int kc = k >> 5, kin = k & 31;
        int cc = kin >> 3;
        int pos = ((cc ^ ((n >> 1) & 3)) << 3) | (kin & 7);
        size_t dst = (((size_t)l * NCH2 + kc) * 320 + n) * 32 + pos;
        g_B2h[dst] = h;
        g_B2l[dst] = __float2bfloat16(w - __bfloat162float(h));
    }
    if (idx < NLAYER * NB2) {
        int n = idx % NB2, l = idx / NB2;
        g_b2p[idx] = (n < 300) ? b2[l * 300 + n] : 0.f;
    }
}

__global__ void k_prep_small(const float* __restrict__ e1, const float* __restrict__ e2) {
    int idx = blockIdx.x * blockDim.x + threadIdx.x;
    if (idx < NLAYER * 6 * KA) {
        int c = idx % KA, r = idx / KA;
        g_e1p[idx] = (c < 300) ? e1[(size_t)r * 300 + c] : 0.f;
    }
    if (idx < NLAYER * 3 * KA) {
        int c = idx % KA, r = idx / KA;
        g_e2p[idx] = (c < 300) ? e2[(size_t)r * 300 + c] : 0.f;
    }
    if (idx < KA) { g_scale[idx] = 1.f; g_shift[idx] = 0.f; }
    if (idx < 2 * KA) g_stats[idx] = 0.f;
}

__global__ void k_count(const int* __restrict__ edge_index, const int* __restrict__ edge_attr) {
    int e = blockIdx.x * blockDim.x + threadIdx.x;
    if (e >= NEDGE) return;
    int dst = edge_index[NEDGE + e];
    int a0 = edge_attr[2 * e];
    int a1 = edge_attr[2 * e + 1];
    atomicAdd(&g_deg[dst], 1);
    atomicAdd(&g_ecnt[(size_t)dst * 9 + a0], 1);
    atomicAdd(&g_ecnt[(size_t)dst * 9 + 6 + a1], 1);
}

__global__ void k_scan() {
    __shared__ int wsum[32];
    __shared__ int carry;
    int t = threadIdx.x;
    int lane = t & 31, w = t >> 5;
    if (t == 0) carry = 0;
    __syncthreads();
    for (int base = 0; base < NNODE; base += 1024) {
        int v = (base + t < NNODE) ? g_deg[base + t] : 0;
        int s = v;
        #pragma unroll
        for (int o = 1; o < 32; o <<= 1) {
            int u = __shfl_up_sync(0xffffffffu, s, o);
            if (lane >= o) s += u;
        }
        if (lane == 31) wsum[w] = s;
        __syncthreads();
        if (w == 0) {
            int ws = wsum[lane];
            #pragma unroll
            for (int o = 1; o < 32; o <<= 1) {
                int u = __shfl_up_sync(0xffffffffu, ws, o);
                if (lane >= o) ws += u;
            }
            wsum[lane] = ws;
        }
        __syncthreads();
        int excl = s - v + (w > 0 ? wsum[w - 1] : 0) + carry;
        if (base + t < NNODE) g_rowptr[base + t] = excl;
        int total = wsum[31];
        __syncthreads();
        if (t == 0) carry += total;
        __syncthreads();
    }
    if (t == 0) g_rowptr[NNODE] = carry;
}

__global__ void k_fill(const int* __restrict__ edge_index) {
    int e = blockIdx.x * blockDim.x + threadIdx.x;
    if (e >= NEDGE) return;
    int dst = edge_index[NEDGE + e];
    int src = edge_index[e];
    int pos = g_rowptr[dst] + atomicAdd(&g_cursor[dst], 1);
    g_srclist[pos] = src;
}

__global__ void k_h0(const int* __restrict__ x,
                     const float* __restrict__ emb1, const float* __restrict__ emb2) {
    size_t idx = (size_t)blockIdx.x * blockDim.x + threadIdx.x;
    if (idx >= (size_t)NNODE * KA) return;
    int c = (int)(idx % KA);
    int i = (int)(idx / KA);
    if (c < 300) {
        int a0 = x[2 * i], a1 = x[2 * i + 1];
        g_h2[idx] = emb1[(size_t)a0 * 300 + c] + emb2[(size_t)a1 * 300 + c];
    } else {
        g_h2[idx] = 0.f;
    }
}

__global__ void k_gstart(const int* __restrict__ batch) {
    int i = blockIdx.x * blockDim.x + threadIdx.x;
    if (i >= NNODE) return;
    int b = batch[i];
    int bp = (i == 0) ? -1 : batch[i - 1];
    for (int g = bp + 1; g <= b; g++) g_gstart[g] = i;
    if (i == NNODE - 1) {
        for (int g = b + 1; g <= NGRAPH; g++) g_gstart[g] = NNODE;
    }
}

__global__ void k_ginv() {
    int g = blockIdx.x * blockDim.x + threadIdx.x;
    if (g >= NGRAPH) return;
    int c = g_gstart[g + 1] - g_gstart[g];
    g_ginv[g] = (c > 0) ? (1.f / (float)c) : 0.f;
}

// ---------------- aggregation (BN-affine fused; writes chunk-major swizzled bf16 hi/lo) ----------------
__global__ void k_agg(int l, int relu) {
    int i = blockIdx.x;
    int t = threadIdx.x;     // 96 threads; 80 write (75 compute + 5 zero-pad)
    __shared__ int scnt[9];
    __shared__ int srange[2];
    if (t < 9) scnt[t] = g_ecnt[(size_t)i * 9 + t];
    else if (t == 9) srange[0] = g_rowptr[i];
    else if (t == 10) srange[1] = g_rowptr[i + 1];
    __syncthreads();
    if (t >= 80) return;
    float4 acc = make_float4(0.f, 0.f, 0.f, 0.f);
    if (t < 75) {
        const float4* h2v = (const float4*)g_h2;
        const float4* e1v = (const float4*)(g_e1p + l * 6 * KA);
        const float4* e2v = (const float4*)(g_e2p + l * 3 * KA);
        float4 sc = ((const float4*)g_scale)[t];
        float4 sh = ((const float4*)g_shift)[t];
        {   // self loop
            float4 xx = h2v[(size_t)i * 76 + t];
            acc.x = fmaf(xx.x, sc.x, sh.x);
            acc.y = fmaf(xx.y, sc.y, sh.y);
            acc.z = fmaf(xx.z, sc.z, sh.z);
            acc.w = fmaf(xx.w, sc.w, sh.w);
            if (relu) {
                acc.x = fmaxf(acc.x, 0.f); acc.y = fmaxf(acc.y, 0.f);
                acc.z = fmaxf(acc.z, 0.f); acc.w = fmaxf(acc.w, 0.f);
            }
        }
        #pragma unroll
        for (int tt = 0; tt < 6; tt++) {
            float ct = (float)(scnt[tt] + (tt == 0 ? 1 : 0));
            if (ct != 0.f) {
                float4 e = e1v[tt * 76 + t];
                acc.x = fmaf(ct, e.x, acc.x); acc.y = fmaf(ct, e.y, acc.y);
                acc.z = fmaf(ct, e.z, acc.z); acc.w = fmaf(ct, e.w, acc.w);
            }
        }
        #pragma unroll
        for (int dd = 0; dd < 3; dd++) {
            float cd = (float)(scnt[6 + dd] + (dd == 0 ? 1 : 0));
            if (cd != 0.f) {
                float4 e = e2v[dd * 76 + t];
                acc.x = fmaf(cd, e.x, acc.x); acc.y = fmaf(cd, e.y, acc.y);
                acc.z = fmaf(cd, e.z, acc.z); acc.w = fmaf(cd, e.w, acc.w);
            }
        }
        for (int p = srange[0]; p < srange[1]; p++) {
            int j = g_srclist[p];
            float4 xx = h2v[(size_t)j * 76 + t];
            float4 a;
            a.x = fmaf(xx.x, sc.x, sh.x);
            a.y = fmaf(xx.y, sc.y, sh.y);
            a.z = fmaf(xx.z, sc.z, sh.z);
            a.w = fmaf(xx.w, sc.w, sh.w);
            if (relu) {
                a.x = fmaxf(a.x, 0.f); a.y = fmaxf(a.y, 0.f);
                a.z = fmaxf(a.z, 0.f); a.w = fmaxf(a.w, 0.f);
            }
            acc.x += a.x; acc.y += a.y; acc.z += a.z; acc.w += a.w;
        }
    }
    // bf16 hi/lo split, chunk-major swizzled write (thread t covers cols 4t..4t+3)
    __nv_bfloat162 h01, h23, l01, l23;
    h01.x = __float2bfloat16(acc.x); l01.x = __float2bfloat16(acc.x - __bfloat162float(h01.x));
    h01.y = __float2bfloat16(acc.y); l01.y = __float2bfloat16(acc.y - __bfloat162float(h01.y));
    h23.x = __float2bfloat16(acc.z); l23.x = __float2bfloat16(acc.z - __bfloat162float(h23.x));
    h23.y = __float2bfloat16(acc.w); l23.y = __float2bfloat16(acc.w - __bfloat162float(h23.y));
    int kc = t >> 3;                     // chunk of 32 cols
    int bo = (8 * t) & 63;               // byte offset within 64B row (pre-swizzle)
    int cc = bo >> 4;
    int swbo = ((cc ^ ((i >> 1) & 3)) << 4) | (bo & 15);
    size_t base = ((size_t)kc * NPAD + i) * 64 + swbo;
    char* dh = (char*)g_aggh + base;
    char* dl = (char*)g_aggl + base;
    *(__nv_bfloat162*)(dh) = h01;
    *(__nv_bfloat162*)(dh + 4) = h23;
    *(__nv_bfloat162*)(dl) = l01;
    *(__nv_bfloat162*)(dl + 4) = l23;
}

// ---------------- mma.sync bf16-split GEMM (3-stage, bulk loads, warp-decoupled mbarrier pipeline) ----------------
// Block 128x160, 8 warps (2M x 4N), warp tile 64x40, K-chunk 32.
// D = Ah@Bh + Al@Bh + Ah@Bl (fp32 acc).
// which==0: T = relu(agg @ W1 + b1) -> chunk-major bf16 hi/lo   (K=320, 10 chunks)
// which==1: h2 = T @ W2 + b2        -> fp32 + fused BN stats    (K=608, 19 chunks)
#define OFF_AH 0
#define OFF_AL 8192
#define OFF_BH 16384
#define OFF_BL 26624
#define BUF_B  36864
#define MB_OFF (3 * BUF_B)
#define SM_TOTAL (3 * BUF_B + 64)
#define TX_BYTES 36864u

__global__ void __launch_bounds__(256, 2)
k_gemm(int which, int l) {
    extern __shared__ char smem[];
    uint32_t sbase = smem_u32(smem);
    int tid = threadIdx.x;
    int wid = tid >> 5;
    int lane = tid & 31;
    int m0 = blockIdx.y * 128;
    int n0 = blockIdx.x * 160;
    int wm0 = (wid & 1) * 64;
    int wn0 = (wid >> 1) * 40;

    const char *pAh, *pAl, *pBh, *pBl;
    const float* bias;
    size_t szAch = (size_t)NPAD * 64;
    size_t szBch;
    int nchunk;
    if (which == 0) {
        pAh = (const char*)g_aggh; pAl = (const char*)g_aggl;
        pBh = (const char*)g_B1h + (size_t)l * (NCH1 * 640 * 32) * 2;
        pBl = (const char*)g_B1l + (size_t)l * (NCH1 * 640 * 32) * 2;
        szBch = 640 * 64;
        bias = g_b1p + l * NB1; nchunk = NCH1;
    } else {
        pAh = (const char*)g_Th; pAl = (const char*)g_Tl;
        pBh = (const char*)g_B2h + (size_t)l * (NCH2 * 320 * 32) * 2;
        pBl = (const char*)g_B2l + (size_t)l * (NCH2 * 320 * 32) * 2;
        szBch = 320 * 64;
        bias = g_b2p + l * NB2; nchunk = NCH2;
    }

    // mbarriers: full[3] at +0,+8,+16 (tx-based); empty[3] at +24,+32,+40 (count=8 warps)
    if (tid == 0) {
        MBARRIER_INIT(sbase + MB_OFF + 0, 1);
        MBARRIER_INIT(sbase + MB_OFF + 8, 1);
        MBARRIER_INIT(sbase + MB_OFF + 16, 1);
        MBARRIER_INIT(sbase + MB_OFF + 24, 8);
        MBARRIER_INIT(sbase + MB_OFF + 32, 8);
        MBARRIER_INIT(sbase + MB_OFF + 40, 8);
    }
    __syncthreads();

    auto issue_chunk = [&](int c, int slot) {
        uint32_t bb = sbase + slot * BUF_B;
        uint32_t mb = sbase + MB_OFF + slot * 8;
        MBARRIER_EXPECT_TX(mb, TX_BYTES);
        const char* sa = pAh + (size_t)c * szAch + (size_t)m0 * 64;
        const char* sal = pAl + (size_t)c * szAch + (size_t)m0 * 64;
        const char* sb = pBh + (size_t)c * szBch + (size_t)n0 * 64;
        const char* sbl = pBl + (size_t)c * szBch + (size_t)n0 * 64;
        bulk_g2s(bb + OFF_AH, sa, 8192, mb);
        bulk_g2s(bb + OFF_AL, sal, 8192, mb);
        bulk_g2s(bb + OFF_BH, sb, 10240, mb);
        bulk_g2s(bb + OFF_BL, sbl, 10240, mb);
    };

    if (tid == 0) {
        issue_chunk(0, 0);
        issue_chunk(1, 1);
        if (nchunk > 2) issue_chunk(2, 2);
    }

    float acc[4][5][4];
    #pragma unroll
    for (int a = 0; a < 4; a++)
        #pragma unroll
        for (int b = 0; b < 5; b++)
            #pragma unroll
            for (int c = 0; c < 4; c++) acc[a][b][c] = 0.f;

    int l8 = lane & 7;
    int ars = (lane >> 3) & 1;        // A row +8
    int aks = lane >> 4;              // A k-chunk half (16B index bit)
    int brow4 = (lane & 7) + ((lane >> 4) & 1) * 8;
    int bchalf = (lane >> 3) & 1;     // B k-chunk half

    int slot = 0;
    int fph[3] = {0, 0, 0};           // full parity per slot
    int eph[3] = {0, 0, 0};           // empty parity per slot (producer only)
    for (int c = 0; c < nchunk; c++) {
        MBARRIER_WAIT_PARITY(sbase + MB_OFF + slot * 8, fph[slot]);
        fph[slot] ^= 1;
        uint32_t bb = sbase + slot * BUF_B;
        #pragma unroll
        for (int ks = 0; ks < 2; ks++) {
            uint32_t a_h[4][4], a_l[4][4], b_h[5][2], b_l[5][2];
            {
                int arow = wm0 + l8 + ars * 8;
                int achunk = ks * 2 + aks;
                uint32_t a_addr = bb + swz64(arow, achunk);
                #pragma unroll
                for (int tm = 0; tm < 4; tm++) {
                    ldsm_x4(a_h[tm], a_addr + OFF_AH + tm * 1024);
                    ldsm_x4(a_l[tm], a_addr + OFF_AL + tm * 1024);
                }
            }
            {
                int brow = wn0 + brow4;
                int bchunk = ks * 2 + bchalf;
                uint32_t b_addr4 = bb + swz64(brow, bchunk);
                #pragma unroll
                for (int tn = 0; tn < 4; tn += 2) {
                    ldsm_x4(&b_h[tn][0], b_addr4 + OFF_BH + tn * 512);
                    ldsm_x4(&b_l[tn][0], b_addr4 + OFF_BL + tn * 512);
                }
                int brow2 = wn0 + 32 + l8;
                uint32_t b_addr2 = bb + swz64(brow2, bchunk);
                ldsm_x2(b_h[4], b_addr2 + OFF_BH);
                ldsm_x2(b_l[4], b_addr2 + OFF_BL);
            }
            if (ks == 1) {
                // all smem reads of this slot are complete -> release slot early
                if (lane == 0) MBARRIER_ARRIVE(sbase + MB_OFF + 24 + slot * 8);
            }
            #pragma unroll
            for (int tm = 0; tm < 4; tm++)
                #pragma unroll
                for (int tn = 0; tn < 5; tn++) {
                    mma_bf16(acc[tm][tn], a_h[tm], b_h[tn]);
                    mma_bf16(acc[tm][tn], a_l[tm], b_h[tn]);
                    mma_bf16(acc[tm][tn], a_h[tm], b_l[tn]);
                }
        }
        // producer: refill this slot with chunk c+3 once all warps released it
        if (tid == 0 && c + 3 < nchunk) {
            MBARRIER_WAIT_PARITY(sbase + MB_OFF + 24 + slot * 8, eph[slot]);
            eph[slot] ^= 1;
            issue_chunk(c + 3, slot);
        }
        slot++; if (slot == 3) slot = 0;
    }

    // epilogue
    int gl = lane >> 2;
    int gc = (lane & 3) * 2;
    if (which == 0) {
        #pragma unroll
        for (int tm = 0; tm < 4; tm++) {
            #pragma unroll
            for (int half = 0; half < 2; half++) {
                int row = m0 + wm0 + tm * 16 + gl + half * 8;
                if (row >= NNODE) continue;
                #pragma unroll
                for (int tn = 0; tn < 5; tn++) {
                    int col = n0 + wn0 + tn * 8 + gc;
                    if (col >= 608) continue;
                    float v0 = acc[tm][tn][half * 2 + 0] + bias[col];
                    float v1 = acc[tm][tn][half * 2 + 1] + bias[col + 1];
                    v0 = fmaxf(v0, 0.f);
                    v1 = fmaxf(v1, 0.f);
                    __nv_bfloat162 hv, lv;
                    hv.x = __float2bfloat16(v0); lv.x = __float2bfloat16(v0 - __bfloat162float(hv.x));
                    hv.y = __float2bfloat16(v1); lv.y = __float2bfloat16(v1 - __bfloat162float(hv.y));
                    // chunk-major swizzled write
                    int kc = col >> 5;
                    int bo = (col & 31) * 2;
                    int cc = bo >> 4;
                    int swbo = ((cc ^ ((row >> 1) & 3)) << 4) | (bo & 15);
                    size_t base = ((size_t)kc * NPAD + row) * 64 + swbo;
                    *(__nv_bfloat162*)((char*)g_Th + base) = hv;
                    *(__nv_bfloat162*)((char*)g_Tl + base) = lv;
                }
            }
        }
    } else {
        float cs[5][2], cq[5][2];
        #pragma unroll
        for (int tn = 0; tn < 5; tn++) {
            cs[tn][0] = 0.f; cs[tn][1] = 0.f;
            cq[tn][0] = 0.f; cq[tn][1] = 0.f;
        }
        #pragma unroll
        for (int tm = 0; tm < 4; tm++) {
            #pragma unroll
            for (int half = 0; half < 2; half++) {
                int row = m0 + wm0 + tm * 16 + gl + half * 8;
                if (row >= NNODE) continue;
                #pragma unroll
                for (int tn = 0; tn < 5; tn++) {
                    int col = n0 + wn0 + tn * 8 + gc;
                    float v0 = acc[tm][tn][half * 2 + 0] + bias[col];
                    float v1 = acc[tm][tn][half * 2 + 1] + bias[col + 1];
                    if (col < KA) {
                        float2 v; v.x = v0; v.y = v1;
                        *(float2*)(g_h2 + (size_t)row * KA + col) = v;
                    }
                    cs[tn][0] += v0; cq[tn][0] = fmaf(v0, v0, cq[tn][0]);
                    cs[tn][1] += v1; cq[tn][1] = fmaf(v1, v1, cq[tn][1]);
                }
            }
        }
        #pragma unroll
        for (int off = 4; off < 32; off <<= 1) {
            #pragma unroll
            for (int tn = 0; tn < 5; tn++) {
                cs[tn][0] += __shfl_xor_sync(0xffffffffu, cs[tn][0], off);
                cs[tn][1] += __shfl_xor_sync(0xffffffffu, cs[tn][1], off);
                cq[tn][0] += __shfl_xor_sync(0xffffffffu, cq[tn][0], off);
                cq[tn][1] += __shfl_xor_sync(0xffffffffu, cq[tn][1], off);
            }
        }
        if (lane < 4) {
            #pragma unroll
            for (int tn = 0; tn < 5; tn++) {
                #pragma unroll
                for (int j = 0; j < 2; j++) {
                    int col = n0 + wn0 + tn * 8 + lane * 2 + j;
                    if (col < KA) {
                        atomicAdd(&g_stats[col], cs[tn][j]);
                        atomicAdd(&g_stats[KA + col], cq[tn][j]);
                    }
                }
            }
        }
    }
}

// computes affine for this layer, then zeroes stats for the next layer
__global__ void k_bn(const float* __restrict__ gamma, const float* __restrict__ beta, int l) {
    int c = threadIdx.x;
    if (c >= KA) return;
    if (c < 300) {
        float mu = g_stats[c] * (1.f / NNODE);
        float var = g_stats[KA + c] * (1.f / NNODE) - mu * mu;
        float rstd = rsqrtf(var + 1e-5f);
        float sc = rstd * gamma[l * 300 + c];
        g_scale[c] = sc;
        g_shift[c] = beta[l * 300 + c] - mu * sc;
    } else {
        g_scale[c] = 0.f;
        g_shift[c] = 0.f;
    }
    g_stats[c] = 0.f;
    g_stats[KA + c] = 0.f;
}

__global__ void k_pool(float* __restrict__ out) {
    int g = blockIdx.x;
    int t = threadIdx.x;
    if (t >= 75) return;
    int i0 = g_gstart[g], i1 = g_gstart[g + 1];
    const float4* h2v = (const float4*)g_h2;
    float4 sc = ((const float4*)g_scale)[t];
    float4 sh = ((const float4*)g_shift)[t];
    float4 acc = make_float4(0.f, 0.f, 0.f, 0.f);
    for (int i = i0; i < i1; i++) {
        float4 xx = h2v[(size_t)i * 76 + t];
        acc.x += fmaf(xx.x, sc.x, sh.x);
        acc.y += fmaf(xx.y, sc.y, sh.y);
        acc.z += fmaf(xx.z, sc.z, sh.z);
        acc.w += fmaf(xx.w, sc.w, sh.w);
    }
    float inv = g_ginv[g];
    acc.x *= inv; acc.y *= inv; acc.z *= inv; acc.w *= inv;
    ((float4*)out)[(size_t)g * 75 + t] = acc;
}

// ---------------- host launcher ----------------
extern "C" void kernel_launch(void* const* d_in, const int* in_sizes, int n_in,
                              void* d_out, int out_size) {
    const int* x          = (const int*)d_in[0];
    const int* edge_index = (const int*)d_in[1];
    const int* edge_attr  = (const int*)d_in[2];
    const int* batch      = (const int*)d_in[3];
    const float* x_emb1   = (const float*)d_in[4];
    const float* x_emb2   = (const float*)d_in[5];
    const float* e1       = (const float*)d_in[6];
    const float* e2       = (const float*)d_in[7];
    const float* W1       = (const float*)d_in[8];
    const float* b1       = (const float*)d_in[9];
    const float* W2       = (const float*)d_in[10];
    const float* b2       = (const float*)d_in[11];
    const float* gamma    = (const float*)d_in[12];
    const float* beta     = (const float*)d_in[13];
    float* out = (float*)d_out;

    static int smem_set = 0;
    if (!smem_set) {
        cudaFuncSetAttribute(k_gemm, cudaFuncAttributeMaxDynamicSharedMemorySize, SM_TOTAL);
        smem_set = 1;
    }

    k_zero<<<(NNODE * 9 + 255) / 256, 256>>>();
    k_prep_b1<<<(NLAYER * 640 * 320 + 255) / 256, 256>>>(W1, b1);
    k_prep_b2<<<(NLAYER * 320 * 608 + 255) / 256, 256>>>(W2, b2);
    k_prep_small<<<(NLAYER * 6 * KA + 255) / 256, 256>>>(e1, e2);
    k_count<<<(NEDGE + 255) / 256, 256>>>(edge_index, edge_attr);
    k_scan<<<1, 1024>>>();
    k_fill<<<(NEDGE + 255) / 256, 256>>>(edge_index);
    k_h0<<<(int)(((size_t)NNODE * KA + 255) / 256), 256>>>(x, x_emb1, x_emb2);
    k_gstart<<<(NNODE + 255) / 256, 256>>>(batch);
    k_ginv<<<(NGRAPH + 255) / 256, 256>>>();

    for (int l = 0; l < NLAYER; l++) {
        k_agg<<<NNODE, 96>>>(l, (l > 0) ? 1 : 0);
        dim3 g1(4, (NNODE + 127) / 128);
        k_gemm<<<g1, 256, SM_TOTAL>>>(0, l);
        dim3 g2(2, (NNODE + 127) / 128);
        k_gemm<<<g2, 256, SM_TOTAL>>>(1, l);
        k_bn<<<1, 320>>>(gamma, beta, l);
    }
    k_pool<<<NGRAPH, 96>>>(out);
}

// round 15
// speedup vs baseline: 1.1486x; 1.1486x over previous
#include <cuda_runtime.h>
#include <cuda_bf16.h>
#include <cstdint>

#define NNODE 100000
#define NPAD  100096
#define NEDGE 200000
#define NGRAPH 5000
#define NLAYER 5
#define KA 304      // h2 fp32 stride (300 padded to 304)
#define NCH1 10     // K chunks for GEMM1 (K=320)
#define NCH2 19     // K chunks for GEMM2 (K=608)
#define NB1 640
#define NB2 320

// ---------------- device scratch ----------------
// chunk-major, pre-swizzled operand arrays: [kchunk][row][32 bf16]
__device__ float g_h2[(size_t)NNODE * KA];                  // pre-norm layer output (fp32)
__device__ __nv_bfloat16 g_aggh[(size_t)NCH1 * NPAD * 32];  // agg split hi
__device__ __nv_bfloat16 g_aggl[(size_t)NCH1 * NPAD * 32];  // agg split lo
__device__ __nv_bfloat16 g_Th[(size_t)NCH2 * NPAD * 32];    // hidden split hi
__device__ __nv_bfloat16 g_Tl[(size_t)NCH2 * NPAD * 32];    // hidden split lo
__device__ __nv_bfloat16 g_B1h[NLAYER * NCH1 * 640 * 32];   // W1^T split [l][kc][n][32]
__device__ __nv_bfloat16 g_B1l[NLAYER * NCH1 * 640 * 32];
__device__ __nv_bfloat16 g_B2h[NLAYER * NCH2 * 320 * 32];   // W2^T split [l][kc][n][32]
__device__ __nv_bfloat16 g_B2l[NLAYER * NCH2 * 320 * 32];
__device__ float g_b1p[NLAYER * NB1];
__device__ float g_b2p[NLAYER * NB2];
__device__ float g_e1p[NLAYER * 6 * KA];
__device__ float g_e2p[NLAYER * 3 * KA];
__device__ float g_scale[KA];
__device__ float g_shift[KA];
__device__ float g_stats[2 * KA];
__device__ int   g_deg[NNODE];
__device__ int   g_cursor[NNODE];
__device__ int   g_rowptr[NNODE + 1];
__device__ int   g_srclist[NEDGE];
__device__ int   g_ecnt[(size_t)NNODE * 9];
__device__ int   g_gstart[NGRAPH + 1];
__device__ float g_ginv[NGRAPH];

// ---------------- helpers ----------------
__device__ __forceinline__ uint32_t smem_u32(const void* p) {
    uint32_t a;
    asm("{ .reg .u64 t; cvta.to.shared.u64 t, %1; cvt.u32.u64 %0, t; }" : "=r"(a) : "l"(p));
    return a;
}
__device__ __forceinline__ void bulk_g2s(uint32_t dst, const void* src, uint32_t bytes, uint32_t mbar) {
    asm volatile("cp.async.bulk.shared::cta.global.mbarrier::complete_tx::bytes [%0], [%1], %2, [%3];"
                 :: "r"(dst), "l"(src), "r"(bytes), "r"(mbar) : "memory");
}
#define MBARRIER_INIT(addr, cnt) \
    asm volatile("mbarrier.init.shared.b64 [%0], %1;" :: "r"(addr), "r"(cnt) : "memory")
#define MBARRIER_EXPECT_TX(addr, bytes) \
    asm volatile("mbarrier.arrive.expect_tx.shared.b64 _, [%0], %1;" :: "r"(addr), "r"(bytes) : "memory")
#define MBARRIER_WAIT_PARITY(mbar_smem_addr, phase_parity) do { \
    uint32_t _mbar = (uint32_t)(mbar_smem_addr); \
    uint32_t _parity = (uint32_t)(phase_parity); \
    uint32_t _done; \
    asm volatile("{\n\t.reg .pred p;\n\t" \
        "mbarrier.try_wait.parity.acquire.cta.shared::cta.b64 p, [%1], %2;\n\t" \
        "selp.b32 %0, 1, 0, p;\n\t}" \
        : "=r"(_done) : "r"(_mbar), "r"(_parity) : "memory"); \
    if (!_done) { \
        asm volatile("{\n\t.reg .pred P1;\n\t" \
            "WAIT_LOOP_%=:\n\t" \
            "mbarrier.try_wait.parity.acquire.cta.shared::cta.b64 P1, [%0], %1, 0x989680;\n\t" \
            "@P1 bra.uni WAIT_DONE_%=;\n\t" \
            "bra.uni WAIT_LOOP_%=;\n\t" \
            "WAIT_DONE_%=:\n\t}" \
            :: "r"(_mbar), "r"(_parity) : "memory"); \
    } \
} while (0)

__device__ __forceinline__ void ldsm_x4(uint32_t* r, uint32_t addr) {
    asm volatile("ldmatrix.sync.aligned.m8n8.x4.shared.b16 {%0,%1,%2,%3}, [%4];"
                 : "=r"(r[0]), "=r"(r[1]), "=r"(r[2]), "=r"(r[3]) : "r"(addr));
}
__device__ __forceinline__ void ldsm_x2(uint32_t* r, uint32_t addr) {
    asm volatile("ldmatrix.sync.aligned.m8n8.x2.shared.b16 {%0,%1}, [%2];"
                 : "=r"(r[0]), "=r"(r[1]) : "r"(addr));
}
__device__ __forceinline__ void mma_bf16(float* d, const uint32_t* a, const uint32_t* b) {
    asm volatile("mma.sync.aligned.m16n8k16.row.col.f32.bf16.bf16.f32 "
                 "{%0,%1,%2,%3}, {%4,%5,%6,%7}, {%8,%9}, {%0,%1,%2,%3};"
                 : "+f"(d[0]), "+f"(d[1]), "+f"(d[2]), "+f"(d[3])
                 : "r"(a[0]), "r"(a[1]), "r"(a[2]), "r"(a[3]), "r"(b[0]), "r"(b[1]));
}

// swizzled byte offset within a tile: row r (64B rows), 16B chunk cc (0..3)
__device__ __forceinline__ uint32_t swz64(int r, int cc) {
    return (uint32_t)(r * 64 + ((cc ^ ((r >> 1) & 3)) << 4));
}

// ---------------- setup kernels ----------------
__global__ void k_zero() {
    int idx = blockIdx.x * blockDim.x + threadIdx.x;
    if (idx < NNODE) { g_deg[idx] = 0; g_cursor[idx] = 0; }
    if (idx < NNODE * 9) g_ecnt[idx] = 0;
}

__global__ void k_prep_b1(const float* __restrict__ W1, const float* __restrict__ b1) {
    int idx = blockIdx.x * blockDim.x + threadIdx.x;
    if (idx < NLAYER * 640 * 320) {
        int k = idx % 320;
        int n = (idx / 320) % 640;
        int l = idx / (320 * 640);
        float w = (k < 300 && n < 600) ? W1[((size_t)l * 300 + k) * 600 + n] : 0.f;
        __nv_bfloat16 h = __float2bfloat16(w);
        int kc = k >> 5, kin = k & 31;
        int cc = kin >> 3;
        int pos = ((cc ^ ((n >> 1) & 3)) << 3) | (kin & 7);
        size_t dst = (((size_t)l * NCH1 + kc) * 640 + n) * 32 + pos;
        g_B1h[dst] = h;
        g_B1l[dst] = __float2bfloat16(w - __bfloat162float(h));
    }
    if (idx < NLAYER * NB1) {
        int n = idx % NB1, l = idx / NB1;
        g_b1p[idx] = (n < 600) ? b1[l * 600 + n] : 0.f;
    }
}

__global__ void k_prep_b2(const float* __restrict__ W2, const float* __restrict__ b2) {
    int idx = blockIdx.x * blockDim.x + threadIdx.x;
    if (idx < NLAYER * 320 * 608) {
        int k = idx % 608;
        int n = (idx / 608) % 320;
        int l = idx / (608 * 320);
        float w = (k < 600 && n < 300) ? W2[((size_t)l * 600 + k) * 300 + n] : 0.f;
        __nv_bfloat16 h = __float2bfloat16(w);
        int kc = k >> 5, kin = k & 31;
        int cc = kin >> 3;
        int pos = ((cc ^ ((n >> 1) & 3)) << 3) | (kin & 7);
        size_t dst = (((size_t)l * NCH2 + kc) * 320 + n) * 32 + pos;
        g_B2h[dst] = h;
        g_B2l[dst] = __float2bfloat16(w - __bfloat162float(h));
    }
    if (idx < NLAYER * NB2) {
        int n = idx % NB2, l = idx / NB2;
        g_b2p[idx] = (n < 300) ? b2[l * 300 + n] : 0.f;
    }
}

__global__ void k_prep_small(const float* __restrict__ e1, const float* __restrict__ e2) {
    int idx = blockIdx.x * blockDim.x + threadIdx.x;
    if (idx < NLAYER * 6 * KA) {
        int c = idx % KA, r = idx / KA;
        g_e1p[idx] = (c < 300) ? e1[(size_t)r * 300 + c] : 0.f;
    }
    if (idx < NLAYER * 3 * KA) {
        int c = idx % KA, r = idx / KA;
        g_e2p[idx] = (c < 300) ? e2[(size_t)r * 300 + c] : 0.f;
    }
    if (idx < KA) { g_scale[idx] = 1.f; g_shift[idx] = 0.f; }
    if (idx < 2 * KA) g_stats[idx] = 0.f;
}

__global__ void k_count(const int* __restrict__ edge_index, const int* __restrict__ edge_attr) {
    int e = blockIdx.x * blockDim.x + threadIdx.x;
    if (e >= NEDGE) return;
    int dst = edge_index[NEDGE + e];
    int a0 = edge_attr[2 * e];
    int a1 = edge_attr[2 * e + 1];
    atomicAdd(&g_deg[dst], 1);
    atomicAdd(&g_ecnt[(size_t)dst * 9 + a0], 1);
    atomicAdd(&g_ecnt[(size_t)dst * 9 + 6 + a1], 1);
}

__global__ void k_scan() {
    __shared__ int wsum[32];
    __shared__ int carry;
    int t = threadIdx.x;
    int lane = t & 31, w = t >> 5;
    if (t == 0) carry = 0;
    __syncthreads();
    for (int base = 0; base < NNODE; base += 1024) {
        int v = (base + t < NNODE) ? g_deg[base + t] : 0;
        int s = v;
        #pragma unroll
        for (int o = 1; o < 32; o <<= 1) {
            int u = __shfl_up_sync(0xffffffffu, s, o);
            if (lane >= o) s += u;
        }
        if (lane == 31) wsum[w] = s;
        __syncthreads();
        if (w == 0) {
            int ws = wsum[lane];
            #pragma unroll
            for (int o = 1; o < 32; o <<= 1) {
                int u = __shfl_up_sync(0xffffffffu, ws, o);
                if (lane >= o) ws += u;
            }
            wsum[lane] = ws;
        }
        __syncthreads();
        int excl = s - v + (w > 0 ? wsum[w - 1] : 0) + carry;
        if (base + t < NNODE) g_rowptr[base + t] = excl;
        int total = wsum[31];
        __syncthreads();
        if (t == 0) carry += total;
        __syncthreads();
    }
    if (t == 0) g_rowptr[NNODE] = carry;
}

__global__ void k_fill(const int* __restrict__ edge_index) {
    int e = blockIdx.x * blockDim.x + threadIdx.x;
    if (e >= NEDGE) return;
    int dst = edge_index[NEDGE + e];
    int src = edge_index[e];
    int pos = g_rowptr[dst] + atomicAdd(&g_cursor[dst], 1);
    g_srclist[pos] = src;
}

__global__ void k_h0(const int* __restrict__ x,
                     const float* __restrict__ emb1, const float* __restrict__ emb2) {
    size_t idx = (size_t)blockIdx.x * blockDim.x + threadIdx.x;
    if (idx >= (size_t)NNODE * KA) return;
    int c = (int)(idx % KA);
    int i = (int)(idx / KA);
    if (c < 300) {
        int a0 = x[2 * i], a1 = x[2 * i + 1];
        g_h2[idx] = emb1[(size_t)a0 * 300 + c] + emb2[(size_t)a1 * 300 + c];
    } else {
        g_h2[idx] = 0.f;
    }
}

__global__ void k_gstart(const int* __restrict__ batch) {
    int i = blockIdx.x * blockDim.x + threadIdx.x;
    if (i >= NNODE) return;
    int b = batch[i];
    int bp = (i == 0) ? -1 : batch[i - 1];
    for (int g = bp + 1; g <= b; g++) g_gstart[g] = i;
    if (i == NNODE - 1) {
        for (int g = b + 1; g <= NGRAPH; g++) g_gstart[g] = NNODE;
    }
}

__global__ void k_ginv() {
    int g = blockIdx.x * blockDim.x + threadIdx.x;
    if (g >= NGRAPH) return;
    int c = g_gstart[g + 1] - g_gstart[g];
    g_ginv[g] = (c > 0) ? (1.f / (float)c) : 0.f;
}

// ---------------- aggregation: warp-per-node, 4 nodes/CTA ----------------
// Each lane owns float4 column-groups e in {lane, lane+32, lane+64} (e<80).
// acc = affine(h2[i]) + e-table terms + sum_j affine(h2[j]); writes bf16 hi/lo
// chunk-major swizzled (same layout as GEMM bulk loads expect).
__global__ void __launch_bounds__(128)
k_agg(int l, int relu) {
    int wid = threadIdx.x >> 5;
    int lane = threadIdx.x & 31;
    int i = blockIdx.x * 4 + wid;
    if (i >= NNODE) return;

    // broadcast loads (same address across lanes -> single transaction)
    int cnt[9];
    #pragma unroll
    for (int q = 0; q < 9; q++) cnt[q] = g_ecnt[(size_t)i * 9 + q];
    int r0 = g_rowptr[i];
    int r1 = g_rowptr[i + 1];

    const float4* h2v = (const float4*)g_h2;
    const float4* e1v = (const float4*)(g_e1p + l * 6 * KA);
    const float4* e2v = (const float4*)(g_e2p + l * 3 * KA);
    const float4* scv = (const float4*)g_scale;
    const float4* shv = (const float4*)g_shift;

    float4 acc[3];
    int ne = (lane + 64 < 76) ? 3 : ((lane + 32 < 76) ? 2 : 1);
    // element indices: e_k = lane + 32*k  (e<76 compute; 76..79 pad handled at write)
    float4 sc[3], sh[3];
    #pragma unroll
    for (int k = 0; k < 3; k++) {
        if (k < ne) {
            int e = lane + 32 * k;
            sc[k] = scv[e];
            sh[k] = shv[e];
            float4 xx = h2v[(size_t)i * 76 + e];
            float4 a;
            a.x = fmaf(xx.x, sc[k].x, sh[k].x);
            a.y = fmaf(xx.y, sc[k].y, sh[k].y);
            a.z = fmaf(xx.z, sc[k].z, sh[k].z);
            a.w = fmaf(xx.w, sc[k].w, sh[k].w);
            if (relu) {
                a.x = fmaxf(a.x, 0.f); a.y = fmaxf(a.y, 0.f);
                a.z = fmaxf(a.z, 0.f); a.w = fmaxf(a.w, 0.f);
            }
            acc[k] = a;
        } else {
            acc[k] = make_float4(0.f, 0.f, 0.f, 0.f);
        }
    }
    // edge-attr histogram terms (+1 on type0/dir0 for the self loop)
    #pragma unroll
    for (int tt = 0; tt < 6; tt++) {
        float ct = (float)(cnt[tt] + (tt == 0 ? 1 : 0));
        if (ct != 0.f) {
            #pragma unroll
            for (int k = 0; k < 3; k++) {
                if (k < ne) {
                    float4 e4 = e1v[tt * 76 + lane + 32 * k];
                    acc[k].x = fmaf(ct, e4.x, acc[k].x);
                    acc[k].y = fmaf(ct, e4.y, acc[k].y);
                    acc[k].z = fmaf(ct, e4.z, acc[k].z);
                    acc[k].w = fmaf(ct, e4.w, acc[k].w);
                }
            }
        }
    }
    #pragma unroll
    for (int dd = 0; dd < 3; dd++) {
        float cd = (float)(cnt[6 + dd] + (dd == 0 ? 1 : 0));
        if (cd != 0.f) {
            #pragma unroll
            for (int k = 0; k < 3; k++) {
                if (k < ne) {
                    float4 e4 = e2v[dd * 76 + lane + 32 * k];
                    acc[k].x = fmaf(cd, e4.x, acc[k].x);
                    acc[k].y = fmaf(cd, e4.y, acc[k].y);
                    acc[k].z = fmaf(cd, e4.z, acc[k].z);
                    acc[k].w = fmaf(cd, e4.w, acc[k].w);
                }
            }
        }
    }
    // neighbor gather (2-3 independent loads in flight per lane)
    for (int p = r0; p < r1; p++) {
        int j = g_srclist[p];
        float4 xx[3];
        #pragma unroll
        for (int k = 0; k < 3; k++)
            if (k < ne) xx[k] = h2v[(size_t)j * 76 + lane + 32 * k];
        #pragma unroll
        for (int k = 0; k < 3; k++) {
            if (k < ne) {
                float4 a;
                a.x = fmaf(xx[k].x, sc[k].x, sh[k].x);
                a.y = fmaf(xx[k].y, sc[k].y, sh[k].y);
                a.z = fmaf(xx[k].z, sc[k].z, sh[k].z);
                a.w = fmaf(xx[k].w, sc[k].w, sh[k].w);
                if (relu) {
                    a.x = fmaxf(a.x, 0.f); a.y = fmaxf(a.y, 0.f);
                    a.z = fmaxf(a.z, 0.f); a.w = fmaxf(a.w, 0.f);
                }
                acc[k].x += a.x; acc[k].y += a.y; acc[k].z += a.z; acc[k].w += a.w;
            }
        }
    }
    // bf16 hi/lo split + chunk-major swizzled write; lanes also cover pad e=75..79 with zeros
    #pragma unroll
    for (int k = 0; k < 3; k++) {
        int e = lane + 32 * k;
        if (e >= 80) continue;
        float4 v = (k < ne) ? acc[k] : make_float4(0.f, 0.f, 0.f, 0.f);
        if (e >= 75) v = make_float4(0.f, 0.f, 0.f, 0.f);
        __nv_bfloat162 h01, h23, l01, l23;
        h01.x = __float2bfloat16(v.x); l01.x = __float2bfloat16(v.x - __bfloat162float(h01.x));
        h01.y = __float2bfloat16(v.y); l01.y = __float2bfloat16(v.y - __bfloat162float(h01.y));
        h23.x = __float2bfloat16(v.z); l23.x = __float2bfloat16(v.z - __bfloat162float(h23.x));
        h23.y = __float2bfloat16(v.w); l23.y = __float2bfloat16(v.w - __bfloat162float(h23.y));
        int kc = e >> 3;
        int bo = (8 * e) & 63;
        int cc = bo >> 4;
        int swbo = ((cc ^ ((i >> 1) & 3)) << 4) | (bo & 15);
        size_t base = ((size_t)kc * NPAD + i) * 64 + swbo;
        char* dh = (char*)g_aggh + base;
        char* dl = (char*)g_aggl + base;
        *(__nv_bfloat162*)(dh) = h01;
        *(__nv_bfloat162*)(dh + 4) = h23;
        *(__nv_bfloat162*)(dl) = l01;
        *(__nv_bfloat162*)(dl + 4) = l23;
    }
}

// ---------------- mma.sync bf16-split GEMM (3-stage, cp.async.bulk loads) ----------------
// Block 128x160, 8 warps (2M x 4N), warp tile 64x40, K-chunk 32.
// D = Ah@Bh + Al@Bh + Ah@Bl (fp32 acc).
// which==0: T = relu(agg @ W1 + b1) -> chunk-major bf16 hi/lo   (K=320, 10 chunks)
// which==1: h2 = T @ W2 + b2        -> fp32 + fused BN stats    (K=608, 19 chunks)
#define OFF_AH 0
#define OFF_AL 8192
#define OFF_BH 16384
#define OFF_BL 26624
#define BUF_B  36864
#define MB_OFF (3 * BUF_B)
#define SM_TOTAL (3 * BUF_B + 64)
#define TX_BYTES 36864u

__global__ void __launch_bounds__(256, 2)
k_gemm(int which, int l) {
    extern __shared__ char smem[];
    uint32_t sbase = smem_u32(smem);
    int tid = threadIdx.x;
    int wid = tid >> 5;
    int lane = tid & 31;
    int m0 = blockIdx.y * 128;
    int n0 = blockIdx.x * 160;
    int wm0 = (wid & 1) * 64;
    int wn0 = (wid >> 1) * 40;

    const char *pAh, *pAl, *pBh, *pBl;
    const float* bias;
    size_t szAch = (size_t)NPAD * 64;
    size_t szBch;
    int nchunk;
    if (which == 0) {
        pAh = (const char*)g_aggh; pAl = (const char*)g_aggl;
        pBh = (const char*)g_B1h + (size_t)l * (NCH1 * 640 * 32) * 2;
        pBl = (const char*)g_B1l + (size_t)l * (NCH1 * 640 * 32) * 2;
        szBch = 640 * 64;
        bias = g_b1p + l * NB1; nchunk = NCH1;
    } else {
        pAh = (const char*)g_Th; pAl = (const char*)g_Tl;
        pBh = (const char*)g_B2h + (size_t)l * (NCH2 * 320 * 32) * 2;
        pBl = (const char*)g_B2l + (size_t)l * (NCH2 * 320 * 32) * 2;
        szBch = 320 * 64;
        bias = g_b2p + l * NB2; nchunk = NCH2;
    }

    // init mbarriers (one per stage)
    if (tid == 0) {
        MBARRIER_INIT(sbase + MB_OFF + 0, 1);
        MBARRIER_INIT(sbase + MB_OFF + 8, 1);
        MBARRIER_INIT(sbase + MB_OFF + 16, 1);
    }
    __syncthreads();

    auto issue_chunk = [&](int c, int slot) {
        uint32_t bb = sbase + slot * BUF_B;
        uint32_t mb = sbase + MB_OFF + slot * 8;
        MBARRIER_EXPECT_TX(mb, TX_BYTES);
        const char* sa = pAh + (size_t)c * szAch + (size_t)m0 * 64;
        const char* sal = pAl + (size_t)c * szAch + (size_t)m0 * 64;
        const char* sb = pBh + (size_t)c * szBch + (size_t)n0 * 64;
        const char* sbl = pBl + (size_t)c * szBch + (size_t)n0 * 64;
        bulk_g2s(bb + OFF_AH, sa, 8192, mb);
        bulk_g2s(bb + OFF_AL, sal, 8192, mb);
        bulk_g2s(bb + OFF_BH, sb, 10240, mb);
        bulk_g2s(bb + OFF_BL, sbl, 10240, mb);
    };

    if (tid == 0) {
        issue_chunk(0, 0);
        issue_chunk(1, 1);
    }

    float acc[4][5][4];
    #pragma unroll
    for (int a = 0; a < 4; a++)
        #pragma unroll
        for (int b = 0; b < 5; b++)
            #pragma unroll
            for (int c = 0; c < 4; c++) acc[a][b][c] = 0.f;

    int l8 = lane & 7;
    int ars = (lane >> 3) & 1;        // A row +8
    int aks = lane >> 4;              // A k-chunk half (16B index bit)
    int brow4 = (lane & 7) + ((lane >> 4) & 1) * 8;
    int bchalf = (lane >> 3) & 1;     // B k-chunk half

    int slot = 0;
    int ph[3] = {0, 0, 0};
    for (int c = 0; c < nchunk; c++) {
        MBARRIER_WAIT_PARITY(sbase + MB_OFF + slot * 8, ph[slot]);
        ph[slot] ^= 1;
        __syncthreads();   // all threads finished reading the slot being refilled below
        if (tid == 0 && c + 2 < nchunk) {
            int snext = slot + 2; if (snext >= 3) snext -= 3;
            issue_chunk(c + 2, snext);
        }
        uint32_t bb = sbase + slot * BUF_B;
        #pragma unroll
        for (int ks = 0; ks < 2; ks++) {
            uint32_t a_h[4][4], a_l[4][4], b_h[5][2], b_l[5][2];
            {
                int arow = wm0 + l8 + ars * 8;
                int achunk = ks * 2 + aks;
                uint32_t a_addr = bb + swz64(arow, achunk);
                #pragma unroll
                for (int tm = 0; tm < 4; tm++) {
                    ldsm_x4(a_h[tm], a_addr + OFF_AH + tm * 1024);
                    ldsm_x4(a_l[tm], a_addr + OFF_AL + tm * 1024);
                }
            }
            {
                int brow = wn0 + brow4;
                int bchunk = ks * 2 + bchalf;
                uint32_t b_addr4 = bb + swz64(brow, bchunk);
                #pragma unroll
                for (int tn = 0; tn < 4; tn += 2) {
                    ldsm_x4(&b_h[tn][0], b_addr4 + OFF_BH + tn * 512);
                    ldsm_x4(&b_l[tn][0], b_addr4 + OFF_BL + tn * 512);
                }
                int brow2 = wn0 + 32 + l8;
                uint32_t b_addr2 = bb + swz64(brow2, bchunk);
                ldsm_x2(b_h[4], b_addr2 + OFF_BH);
                ldsm_x2(b_l[4], b_addr2 + OFF_BL);
            }
            #pragma unroll
            for (int tm = 0; tm < 4; tm++)
                #pragma unroll
                for (int tn = 0; tn < 5; tn++) {
                    mma_bf16(acc[tm][tn], a_h[tm], b_h[tn]);
                    mma_bf16(acc[tm][tn], a_l[tm], b_h[tn]);
                    mma_bf16(acc[tm][tn], a_h[tm], b_l[tn]);
                }
        }
        slot++; if (slot == 3) slot = 0;
    }

    // epilogue
    int gl = lane >> 2;
    int gc = (lane & 3) * 2;
    if (which == 0) {
        #pragma unroll
        for (int tm = 0; tm < 4; tm++) {
            #pragma unroll
            for (int half = 0; half < 2; half++) {
                int row = m0 + wm0 + tm * 16 + gl + half * 8;
                if (row >= NNODE) continue;
                #pragma unroll
                for (int tn = 0; tn < 5; tn++) {
                    int col = n0 + wn0 + tn * 8 + gc;
                    if (col >= 608) continue;
                    float v0 = acc[tm][tn][half * 2 + 0] + bias[col];
                    float v1 = acc[tm][tn][half * 2 + 1] + bias[col + 1];
                    v0 = fmaxf(v0, 0.f);
                    v1 = fmaxf(v1, 0.f);
                    __nv_bfloat162 hv, lv;
                    hv.x = __float2bfloat16(v0); lv.x = __float2bfloat16(v0 - __bfloat162float(hv.x));
                    hv.y = __float2bfloat16(v1); lv.y = __float2bfloat16(v1 - __bfloat162float(hv.y));
                    // chunk-major swizzled write
                    int kc = col >> 5;
                    int bo = (col & 31) * 2;
                    int cc = bo >> 4;
                    int swbo = ((cc ^ ((row >> 1) & 3)) << 4) | (bo & 15);
                    size_t base = ((size_t)kc * NPAD + row) * 64 + swbo;
                    *(__nv_bfloat162*)((char*)g_Th + base) = hv;
                    *(__nv_bfloat162*)((char*)g_Tl + base) = lv;
                }
            }
        }
    } else {
        float cs[5][2], cq[5][2];
        #pragma unroll
        for (int tn = 0; tn < 5; tn++) {
            cs[tn][0] = 0.f; cs[tn][1] = 0.f;
            cq[tn][0] = 0.f; cq[tn][1] = 0.f;
        }
        #pragma unroll
        for (int tm = 0; tm < 4; tm++) {
            #pragma unroll
            for (int half = 0; half < 2; half++) {
                int row = m0 + wm0 + tm * 16 + gl + half * 8;
                if (row >= NNODE) continue;
                #pragma unroll
                for (int tn = 0; tn < 5; tn++) {
                    int col = n0 + wn0 + tn * 8 + gc;
                    float v0 = acc[tm][tn][half * 2 + 0] + bias[col];
                    float v1 = acc[tm][tn][half * 2 + 1] + bias[col + 1];
                    if (col < KA) {
                        float2 v; v.x = v0; v.y = v1;
                        *(float2*)(g_h2 + (size_t)row * KA + col) = v;
                    }
                    cs[tn][0] += v0; cq[tn][0] = fmaf(v0, v0, cq[tn][0]);
                    cs[tn][1] += v1; cq[tn][1] = fmaf(v1, v1, cq[tn][1]);
                }
            }
        }
        #pragma unroll
        for (int off = 4; off < 32; off <<= 1) {
            #pragma unroll
            for (int tn = 0; tn < 5; tn++) {
                cs[tn][0] += __shfl_xor_sync(0xffffffffu, cs[tn][0], off);
                cs[tn][1] += __shfl_xor_sync(0xffffffffu, cs[tn][1], off);
                cq[tn][0] += __shfl_xor_sync(0xffffffffu, cq[tn][0], off);
                cq[tn][1] += __shfl_xor_sync(0xffffffffu, cq[tn][1], off);
            }
        }
        if (lane < 4) {
            #pragma unroll
            for (int tn = 0; tn < 5; tn++) {
                #pragma unroll
                for (int j = 0; j < 2; j++) {
                    int col = n0 + wn0 + tn * 8 + lane * 2 + j;
                    if (col < KA) {
                        atomicAdd(&g_stats[col], cs[tn][j]);
                        atomicAdd(&g_stats[KA + col], cq[tn][j]);
                    }
                }
            }
        }
    }
}

// computes affine for this layer, then zeroes stats for the next layer
__global__ void k_bn(const float* __restrict__ gamma, const float* __restrict__ beta, int l) {
    int c = threadIdx.x;
    if (c >= KA) return;
    if (c < 300) {
        float mu = g_stats[c] * (1.f / NNODE);
        float var = g_stats[KA + c] * (1.f / NNODE) - mu * mu;
        float rstd = rsqrtf(var + 1e-5f);
        float sc = rstd * gamma[l * 300 + c];
        g_scale[c] = sc;
        g_shift[c] = beta[l * 300 + c] - mu * sc;
    } else {
        g_scale[c] = 0.f;
        g_shift[c] = 0.f;
    }
    g_stats[c] = 0.f;
    g_stats[KA + c] = 0.f;
}

__global__ void k_pool(float* __restrict__ out) {
    int g = blockIdx.x;
    int t = threadIdx.x;
    if (t >= 75) return;
    int i0 = g_gstart[g], i1 = g_gstart[g + 1];
    const float4* h2v = (const float4*)g_h2;
    float4 sc = ((const float4*)g_scale)[t];
    float4 sh = ((const float4*)g_shift)[t];
    float4 acc = make_float4(0.f, 0.f, 0.f, 0.f);
    for (int i = i0; i < i1; i++) {
        float4 xx = h2v[(size_t)i * 76 + t];
        acc.x += fmaf(xx.x, sc.x, sh.x);
        acc.y += fmaf(xx.y, sc.y, sh.y);
        acc.z += fmaf(xx.z, sc.z, sh.z);
        acc.w += fmaf(xx.w, sc.w, sh.w);
    }
    float inv = g_ginv[g];
    acc.x *= inv; acc.y *= inv; acc.z *= inv; acc.w *= inv;
    ((float4*)out)[(size_t)g * 75 + t] = acc;
}

// ---------------- host launcher ----------------
extern "C" void kernel_launch(void* const* d_in, const int* in_sizes, int n_in,
                              void* d_out, int out_size) {
    const int* x          = (const int*)d_in[0];
    const int* edge_index = (const int*)d_in[1];
    const int* edge_attr  = (const int*)d_in[2];
    const int* batch      = (const int*)d_in[3];
    const float* x_emb1   = (const float*)d_in[4];
    const float* x_emb2   = (const float*)d_in[5];
    const float* e1       = (const float*)d_in[6];
    const float* e2       = (const float*)d_in[7];
    const float* W1       = (const float*)d_in[8];
    const float* b1       = (const float*)d_in[9];
    const float* W2       = (const float*)d_in[10];
    const float* b2       = (const float*)d_in[11];
    const float* gamma    = (const float*)d_in[12];
    const float* beta     = (const float*)d_in[13];
    float* out = (float*)d_out;

    static int smem_set = 0;
    if (!smem_set) {
        cudaFuncSetAttribute(k_gemm, cudaFuncAttributeMaxDynamicSharedMemorySize, SM_TOTAL);
        smem_set = 1;
    }

    k_zero<<<(NNODE * 9 + 255) / 256, 256>>>();
    k_prep_b1<<<(NLAYER * 640 * 320 + 255) / 256, 256>>>(W1, b1);
    k_prep_b2<<<(NLAYER * 320 * 608 + 255) / 256, 256>>>(W2, b2);
    k_prep_small<<<(NLAYER * 6 * KA + 255) / 256, 256>>>(e1, e2);
    k_count<<<(NEDGE + 255) / 256, 256>>>(edge_index, edge_attr);
    k_scan<<<1, 1024>>>();
    k_fill<<<(NEDGE + 255) / 256, 256>>>(edge_index);
    k_h0<<<(int)(((size_t)NNODE * KA + 255) / 256), 256>>>(x, x_emb1, x_emb2);
    k_gstart<<<(NNODE + 255) / 256, 256>>>(batch);
    k_ginv<<<(NGRAPH + 255) / 256, 256>>>();

    for (int l = 0; l < NLAYER; l++) {
        k_agg<<<(NNODE + 3) / 4, 128>>>(l, (l > 0) ? 1 : 0);
        dim3 g1(4, (NNODE + 127) / 128);
        k_gemm<<<g1, 256, SM_TOTAL>>>(0, l);
        dim3 g2(2, (NNODE + 127) / 128);
        k_gemm<<<g2, 256, SM_TOTAL>>>(1, l);
        k_bn<<<1, 320>>>(gamma, beta, l);
    }
    k_pool<<<NGRAPH, 96>>>(out);
}